// round 1
// baseline (speedup 1.0000x reference)
#include <cuda_runtime.h>
#include <math.h>

#define NX 400
#define NY 400
#define NC (NX*NY)
#define NTOT (2*NC)
#define STEPS 300
#define NBLK 148
#define TPB 512
#define KMAX 5
#define SRC_I 30
#define DET_I 370

// Persistent device state (no allocations allowed)
__device__ float d_Ez[NTOT];
__device__ float d_Hx[NTOT];
__device__ float d_Hy[NTOT];
__device__ float d_ie[NC];       // COURANT / eps
__device__ float d_dampx[NX];
__device__ float d_dampy[NY];
__device__ unsigned g_cnt;
__device__ volatile unsigned g_gen;

// ---------------- setup: permittivity, damp profiles, zero fields, reset barrier ----------------
__global__ void setup_kernel(const float* __restrict__ radius) {
    int idx = blockIdx.x * blockDim.x + threadIdx.x;
    if (idx == 0) { g_cnt = 0; g_gen = 0; }
    if (idx >= NC) return;
    int i = idx / NY;
    int j = idx - i * NY;

    // port membership for column j: ports centered at 80,160,240,320, width 20
    int p   = (j + 10) / 80 - 1;
    int off = (j + 10) - 80 * (p + 1);
    bool inport = (p >= 0 && p < 4 && off < 20);

    float eps = 1.0f;
    if ((i < SRC_I || i >= DET_I) && inport) eps = 2.8f;   // waveguides
    if (i >= 80 && i < 320 && j >= 80 && j < 320) {        // design region
        int X = i - 80, Y = j - 80;
        int a = X / 30, b = Y / 30;                        // unique candidate circle (r<=12 < 15)
        float r = radius[a * 8 + b];
        if (r < 0.3f) r = 0.0f;
        float dx = (float)(X - (15 + 30 * a));
        float dy = (float)(Y - (15 + 30 * b));
        bool inside = (dx * dx + dy * dy) <= r * r;        // NB: r=0 still captures exact center (matches ref)
        eps = inside ? 1.0f : 2.8f;
    }
    d_ie[idx] = 0.5f / eps;

    d_Ez[idx] = 0.f; d_Hx[idx] = 0.f; d_Hy[idx] = 0.f;
    d_Ez[idx + NC] = 0.f; d_Hx[idx + NC] = 0.f; d_Hy[idx + NC] = 0.f;

    if (idx < NX) {
        float v = 1.0f;
        if (idx < 10) {
            float rr = (10 - idx - 0.5f) * 0.1f;
            v = expf(-0.5f * rr * rr * rr);
        } else if (idx >= NX - 10) {
            float rr = (10 - (NX - 1 - idx) - 0.5f) * 0.1f;
            v = expf(-0.5f * rr * rr * rr);
        }
        d_dampx[idx] = v;
        d_dampy[idx] = v;
    }
}

// ---------------- software grid barrier (all NBLK blocks co-resident) ----------------
__device__ __forceinline__ void gridbar(unsigned target) {
    __syncthreads();
    if (threadIdx.x == 0) {
        __threadfence();                       // release: publish this block's stores
        unsigned a = atomicAdd(&g_cnt, 1u);
        if (a == NBLK - 1) {
            atomicExch(&g_cnt, 0u);            // reset for next barrier
            __threadfence();
            g_gen = target;                    // volatile store -> L2
        } else {
            while (g_gen < target) { }         // volatile load spin
        }
        __threadfence();                       // acquire
    }
    __syncthreads();
}

// ---------------- persistent FDTD kernel: whole 300-step sim, both batches ----------------
__global__ void __launch_bounds__(TPB, 1)
fdtd_kernel(const float* __restrict__ phases, float* __restrict__ out)
{
    __shared__ float sdx[NX], sdy[NY];
    for (int k = threadIdx.x; k < NX; k += TPB) { sdx[k] = d_dampx[k]; sdy[k] = d_dampy[k]; }
    __syncthreads();

    const int tid = blockIdx.x * TPB + threadIdx.x;
    const int S   = NBLK * TPB;

    // Per-thread owned cells: fixed for the whole simulation.
    int   cc[KMAX], ii[KMAX], jj[KMAX];
    float dmp[KMAX], ie[KMAX];
    float ez[KMAX], hx[KMAX], hy[KMAX];
    float psrc[KMAX];          // pi*phase for this cell's port (if source row)
    bool  srcf[KMAX];
    int K = 0;
    #pragma unroll
    for (int k = 0; k < KMAX; ++k) {
        int c = tid + k * S;
        cc[k] = c; ii[k] = 0; jj[k] = 0; dmp[k] = 0.f; ie[k] = 0.f;
        ez[k] = 0.f; hx[k] = 0.f; hy[k] = 0.f; psrc[k] = 0.f; srcf[k] = false;
        if (c < NTOT) {
            K = k + 1;
            int sp = (c >= NC) ? c - NC : c;
            int i = sp / NY;
            int j = sp - i * NY;
            ii[k] = i; jj[k] = j;
            dmp[k] = sdx[i] * sdy[j];
            ie[k]  = d_ie[sp];
            int p   = (j + 10) / 80 - 1;
            int off = (j + 10) - 80 * (p + 1);
            bool isrc = (i == SRC_I) && (p >= 0) && (p < 4) && (off < 20);
            srcf[k] = isrc;
            if (isrc) {
                int b = (c >= NC) ? 1 : 0;
                psrc[k] = 3.14159265358979323846f * phases[b * 4 + p];
            }
        }
    }

    // omega_dt = 2*pi*DT/PERIOD, DT/PERIOD = 12.5/1550
    const float W = (float)(2.0 * 3.14159265358979323846 * (12.5 / 1550.0));

    unsigned gen = 0;
    for (int t = 0; t < STEPS; ++t) {
        // ---- H substep: in-place (reads Ez only across cells) ----
        #pragma unroll
        for (int k = 0; k < KMAX; ++k) if (k < K) {
            int c = cc[k];
            float dey = (jj[k] < NY - 1) ? (d_Ez[c + 1]  - ez[k]) : 0.f;
            float dex = (ii[k] < NX - 1) ? (d_Ez[c + NY] - ez[k]) : 0.f;
            hx[k] = dmp[k] * (hx[k] - 0.5f * dey);
            hy[k] = dmp[k] * (hy[k] + 0.5f * dex);
            d_Hx[c] = hx[k];
            d_Hy[c] = hy[k];
        }
        gridbar(++gen);

        // ---- E substep: in-place (reads H only across cells) + soft source ----
        float tf = (float)t;
        #pragma unroll
        for (int k = 0; k < KMAX; ++k) if (k < K) {
            int c = cc[k];
            float dhy = (ii[k] > 0) ? (hy[k] - d_Hy[c - NY]) : 0.f;
            float dhx = (jj[k] > 0) ? (hx[k] - d_Hx[c - 1])  : 0.f;
            float e = dmp[k] * (ez[k] + ie[k] * (dhy - dhx));
            if (srcf[k]) e += sinf(tf * W + psrc[k]);
            ez[k] = e;
            d_Ez[c] = e;
        }
        gridbar(++gen);
    }

    // ---- extract detector line: out[b][p][w] = Ez[b, 370, port_row] ----
    if (blockIdx.x == 0 && threadIdx.x < 160) {
        int b = threadIdx.x / 80;
        int r = threadIdx.x - b * 80;
        int p = r / 20;
        int w = r - p * 20;
        int j = (p + 1) * 80 - 10 + w;
        out[threadIdx.x] = d_Ez[b * NC + DET_I * NY + j];
    }
}

extern "C" void kernel_launch(void* const* d_in, const int* in_sizes, int n_in,
                              void* d_out, int out_size) {
    const float* phases = (const float*)d_in[0];   // (2,4) phases
    const float* radius = (const float*)d_in[1];   // (8,8) radii
    float* out = (float*)d_out;                    // (2,4,20) f32
    setup_kernel<<<(NC + 255) / 256, 256>>>(radius);
    fdtd_kernel<<<NBLK, TPB>>>(phases, out);
}

// round 2
// speedup vs baseline: 2.3790x; 2.3790x over previous
#include <cuda_runtime.h>
#include <math.h>

#define NX 400
#define NY 400
#define NC (NX*NY)
#define STEPS 300
#define NSTRIP 74
#define NBLK (2*NSTRIP)
#define TPB 512
#define KMAX 5
#define SRC_I 30
#define DET_I 370
#define PI_F 3.14159265358979323846f

// Persistent device state (no allocations allowed)
__device__ float d_EzG[2*NC];      // only boundary rows actually consumed cross-block
__device__ float d_HyG[2*NC];
__device__ float d_ie[NC];         // COURANT / eps
__device__ float d_damp1[NX];      // 1-D damp profile (x == y profile)
__device__ unsigned d_hflag[NBLK*32];   // padded: one 128B line per block
__device__ unsigned d_eflag[NBLK*32];

// ---------------- setup: permittivity, damp profile, zero state, reset flags ----------------
__global__ void setup_kernel(const float* __restrict__ radius) {
    int idx = blockIdx.x * blockDim.x + threadIdx.x;
    if (idx < NBLK*32) { d_hflag[idx] = 0u; d_eflag[idx] = 0u; }
    if (idx >= NC) return;
    int i = idx / NY;
    int j = idx - i * NY;

    // port membership: ports centered at 80,160,240,320, width 20
    int p   = (j + 10) / 80 - 1;
    int off = (j + 10) - 80 * (p + 1);
    bool inport = (p >= 0 && p < 4 && off < 20);

    float eps = 1.0f;
    if ((i < SRC_I || i >= DET_I) && inport) eps = 2.8f;
    if (i >= 80 && i < 320 && j >= 80 && j < 320) {
        int X = i - 80, Y = j - 80;
        int a = X / 30, b = Y / 30;
        float r = radius[a * 8 + b];
        if (r < 0.3f) r = 0.0f;
        float dx = (float)(X - (15 + 30 * a));
        float dy = (float)(Y - (15 + 30 * b));
        eps = (dx * dx + dy * dy <= r * r) ? 1.0f : 2.8f;
    }
    d_ie[idx] = 0.5f / eps;

    d_EzG[idx] = 0.f; d_EzG[idx + NC] = 0.f;
    d_HyG[idx] = 0.f; d_HyG[idx + NC] = 0.f;

    if (idx < NX) {
        float v = 1.0f;
        if (idx < 10) {
            float rr = (10 - idx - 0.5f) * 0.1f;
            v = expf(-0.5f * rr * rr * rr);
        } else if (idx >= NX - 10) {
            float rr = (10 - (NX - 1 - idx) - 0.5f) * 0.1f;
            v = expf(-0.5f * rr * rr * rr);
        }
        d_damp1[idx] = v;
    }
}

// ---------------- persistent strip kernel with neighbor flag sync ----------------
__global__ void __launch_bounds__(TPB, 1)
fdtd_kernel(const float* __restrict__ phases, float* __restrict__ out)
{
    __shared__ float sEz[6*NY], sHx[6*NY], sHy[6*NY];

    const int bk    = blockIdx.x;
    const int batch = bk / NSTRIP;
    const int s     = bk - batch * NSTRIP;
    const int r0    = (s * NX) / NSTRIP;
    const int r1    = ((s + 1) * NX) / NSTRIP;
    const int h     = r1 - r0;
    const int ncell = h * NY;
    const bool hasA = (s > 0);
    const bool hasB = (s < NSTRIP - 1);
    const int tid   = threadIdx.x;

    for (int x = tid; x < 6*NY; x += TPB) { sEz[x] = 0.f; sHx[x] = 0.f; sHy[x] = 0.f; }

    volatile unsigned* hfS = &d_hflag[bk * 32];
    volatile unsigned* efS = &d_eflag[bk * 32];
    volatile unsigned* hfA = &d_hflag[(bk - 1) * 32];   // valid iff hasA
    volatile unsigned* efB = &d_eflag[(bk + 1) * 32];   // valid iff hasB
    const float* gHyA = d_HyG + (size_t)batch * NC + (size_t)(r0 - 1) * NY; // iff hasA
    const float* gEzB = d_EzG + (size_t)batch * NC + (size_t)r1 * NY;       // iff hasB
    float* gEzTop = d_EzG + (size_t)batch * NC + (size_t)r0 * NY;
    float* gHyBot = d_HyG + (size_t)batch * NC + (size_t)(r1 - 1) * NY;

    // Per-thread owned cells (fixed for whole simulation)
    int   off_[KMAX], jc[KMAX], oidx[KMAX];
    float dmp[KMAX], iek[KMAX], psrc[KMAX];
    float ez[KMAX], hx[KMAX], hy[KMAX];
    bool  eR[KMAX], eD[KMAX], eU[KMAX], eL[KMAX];
    bool  top[KMAX], bot[KMAX], srcf[KMAX], det[KMAX];
    int K = 0;
    #pragma unroll
    for (int k = 0; k < KMAX; ++k) {
        int idx = tid + k * TPB;
        off_[k] = 0; jc[k] = 0; oidx[k] = 0;
        dmp[k] = 0.f; iek[k] = 0.f; psrc[k] = 0.f;
        ez[k] = hx[k] = hy[k] = 0.f;
        eR[k] = eD[k] = eU[k] = eL[k] = false;
        top[k] = bot[k] = srcf[k] = det[k] = false;
        if (idx < ncell) {
            K = k + 1;
            int l = idx / NY;
            int j = idx - l * NY;
            int i = r0 + l;
            off_[k] = idx; jc[k] = j;
            dmp[k] = d_damp1[i] * d_damp1[j];
            iek[k] = d_ie[i * NY + j];
            eR[k] = (j < NY - 1); eD[k] = (i < NX - 1);
            eU[k] = (i > 0);      eL[k] = (j > 0);
            top[k] = (l == 0);    bot[k] = (l == h - 1);
            int p = (j + 10) / 80 - 1;
            int o2 = (j + 10) - 80 * (p + 1);
            bool inport = (p >= 0 && p < 4 && o2 < 20);
            srcf[k] = (i == SRC_I) && inport;
            det[k]  = (i == DET_I) && inport;
            if (srcf[k]) psrc[k] = PI_F * phases[batch * 4 + p];
            if (det[k])  oidx[k] = batch * 80 + p * 20 + o2;
        }
    }
    __syncthreads();

    const float W = (float)(2.0 * 3.14159265358979323846 * (12.5 / 1550.0));

    for (unsigned t = 1; t <= STEPS; ++t) {
        // ---- H substep: needs Ez (own strip smem + below's top row via global) ----
        #pragma unroll
        for (int k = 0; k < KMAX; ++k) if (k < K) {
            int o = off_[k];
            float ezc = ez[k];
            float ezR = eR[k] ? sEz[o + 1] : ezc;                   // diff -> 0 at j boundary
            float ezD = bot[k] ? (eD[k] ? gEzB[jc[k]] : ezc)        // neighbor strip (fresh: waited last step)
                               : sEz[o + NY];
            hx[k] = dmp[k] * (hx[k] - 0.5f * (ezR - ezc));
            hy[k] = dmp[k] * (hy[k] + 0.5f * (ezD - ezc));
            sHx[o] = hx[k];
            sHy[o] = hy[k];
            if (bot[k]) gHyBot[jc[k]] = hy[k];                      // publish bottom Hy row
        }
        __syncthreads();
        if (tid == 0) {
            __threadfence();
            hfS[0] = t;                                             // publish H done
            if (hasA) while (hfA[0] < t) { }                        // need above's Hy row (and Ez[r0] read)
            __threadfence();
        }
        __syncthreads();

        // ---- E substep: needs H (own strip smem + above's bottom Hy row via global) ----
        float tf = (float)(t - 1);
        #pragma unroll
        for (int k = 0; k < KMAX; ++k) if (k < K) {
            int o = off_[k];
            float hyU = top[k] ? (eU[k] ? gHyA[jc[k]] : hy[k])
                               : sHy[o - NY];
            float hxL = eL[k] ? sHx[o - 1] : hx[k];
            float e = dmp[k] * (ez[k] + iek[k] * ((hy[k] - hyU) - (hx[k] - hxL)));
            if (srcf[k]) e += sinf(tf * W + psrc[k]);
            ez[k] = e;
            sEz[o] = e;
            if (top[k]) gEzTop[jc[k]] = e;                          // publish top Ez row
        }
        __syncthreads();
        if (tid == 0) {
            __threadfence();
            efS[0] = t;                                             // publish E done
            if (hasB) while (efB[0] < t) { }                        // need below's Ez row before next H
            __threadfence();
        }
        __syncthreads();
    }

    // ---- detector: final Ez at row 370 lives in registers of strip s=68 ----
    #pragma unroll
    for (int k = 0; k < KMAX; ++k) if (k < K && det[k]) out[oidx[k]] = ez[k];
}

extern "C" void kernel_launch(void* const* d_in, const int* in_sizes, int n_in,
                              void* d_out, int out_size) {
    const float* phases = (const float*)d_in[0];   // (2,4)
    const float* radius = (const float*)d_in[1];   // (8,8)
    float* out = (float*)d_out;                    // (2,4,20)
    setup_kernel<<<(NC + 255) / 256, 256>>>(radius);
    fdtd_kernel<<<NBLK, TPB>>>(phases, out);
}

// round 3
// speedup vs baseline: 3.0487x; 1.2815x over previous
#include <cuda_runtime.h>
#include <math.h>

#define NX 400
#define NY 400
#define NC (NX*NY)
#define STEPS 300
#define NSTRIP 74
#define NBLK (2*NSTRIP)
#define TPB 512
#define KMAX 5
#define SRC_I 30
#define DET_I 370
#define PI_F 3.14159265358979323846f
#define BND_P (2*NBLK*NY)      // parity stride in d_bnd

// Persistent device state (no allocations allowed)
__device__ float d_ie[NC];                 // COURANT / eps
__device__ float d_damp1[NX];              // 1-D damp profile (x == y)
__device__ float d_bnd[2*2*NBLK*NY];       // [parity][side:0=top,1=bot][blk][j]
__device__ unsigned d_flag[NBLK*32];       // one 128B line per block

__device__ __forceinline__ unsigned ld_acq(const unsigned* p) {
    unsigned v;
    asm volatile("ld.global.acquire.gpu.u32 %0, [%1];" : "=r"(v) : "l"(p) : "memory");
    return v;
}
__device__ __forceinline__ void st_rel(unsigned* p, unsigned v) {
    asm volatile("st.global.release.gpu.u32 [%0], %1;" :: "l"(p), "r"(v) : "memory");
}

// ---------------- setup: eps, damp, zero boundary buffers, reset flags ----------------
__global__ void setup_kernel(const float* __restrict__ radius) {
    int idx = blockIdx.x * blockDim.x + threadIdx.x;
    if (idx < NBLK*32) d_flag[idx] = 0u;
    if (idx < 2*2*NBLK*NY) d_bnd[idx] = 0.f;
    if (idx < NX) {
        float v = 1.0f;
        if (idx < 10) {
            float rr = (10 - idx - 0.5f) * 0.1f;
            v = expf(-0.5f * rr * rr * rr);
        } else if (idx >= NX - 10) {
            float rr = (10 - (NX - 1 - idx) - 0.5f) * 0.1f;
            v = expf(-0.5f * rr * rr * rr);
        }
        d_damp1[idx] = v;
    }
    if (idx >= NC) return;
    int i = idx / NY;
    int j = idx - i * NY;
    int p   = (j + 10) / 80 - 1;
    int off = (j + 10) - 80 * (p + 1);
    bool inport = (p >= 0 && p < 4 && off < 20);
    float eps = 1.0f;
    if ((i < SRC_I || i >= DET_I) && inport) eps = 2.8f;
    if (i >= 80 && i < 320 && j >= 80 && j < 320) {
        int X = i - 80, Y = j - 80;
        int a = X / 30, b = Y / 30;
        float r = radius[a * 8 + b];
        if (r < 0.3f) r = 0.0f;
        float dx = (float)(X - (15 + 30 * a));
        float dy = (float)(Y - (15 + 30 * b));
        eps = (dx * dx + dy * dy <= r * r) ? 1.0f : 2.8f;
    }
    d_ie[idx] = 0.5f / eps;
}

// ---------------- persistent strip kernel: one-step-lagged neighbor sync ----------------
__global__ void __launch_bounds__(TPB, 1)
fdtd_kernel(const float* __restrict__ phases, float* __restrict__ out)
{
    __shared__ float sEz[6*NY], sHx[6*NY], sHy[6*NY];

    const int bk    = blockIdx.x;
    const int batch = bk / NSTRIP;
    const int s     = bk - batch * NSTRIP;
    const int r0    = (s * NX) / NSTRIP;
    const int r1    = ((s + 1) * NX) / NSTRIP;
    const int h     = r1 - r0;
    const int ncell = h * NY;
    const bool hasA = (s > 0);
    const bool hasB = (s < NSTRIP - 1);
    const int tid   = threadIdx.x;
    const int bkA   = hasA ? bk - 1 : bk;
    const int bkB   = hasB ? bk + 1 : bk;

    for (int x = tid; x < 6*NY; x += TPB) { sEz[x] = 0.f; sHx[x] = 0.f; sHy[x] = 0.f; }

    const unsigned* flagA = &d_flag[bkA * 32];
    const unsigned* flagB = &d_flag[bkB * 32];
    unsigned*       flagS = &d_flag[bk * 32];

    // boundary row base pointers (parity added per step)
    const float* rdA = &d_bnd[(0*2 + 1)*NBLK*NY + bkA*NY];  // above's bottom Ez row
    const float* rdB = &d_bnd[(0*2 + 0)*NBLK*NY + bkB*NY];  // below's top Ez row
    float*       wrT = &d_bnd[(0*2 + 0)*NBLK*NY + bk*NY];   // own top Ez row
    float*       wrB = &d_bnd[(0*2 + 1)*NBLK*NY + bk*NY];   // own bottom Ez row

    // Per-thread owned cells (fixed for whole simulation)
    int   off_[KMAX], jc[KMAX], oidx[KMAX];
    float dmp[KMAX], iek[KMAX], psrc[KMAX];
    float ez[KMAX], hx[KMAX], hy[KMAX];
    bool  eR[KMAX], eL[KMAX];
    bool  top[KMAX], bot[KMAX], srcf[KMAX], det[KMAX];
    bool  spinA = false, spinB = false;
    float hyH = 0.f, dmpH = 0.f;          // redundant Hy halo at row r0-1 (top threads, k=0)
    int K = 0;
    #pragma unroll
    for (int k = 0; k < KMAX; ++k) {
        int idx = tid + k * TPB;
        off_[k] = 0; jc[k] = 0; oidx[k] = 0;
        dmp[k] = 0.f; iek[k] = 0.f; psrc[k] = 0.f;
        ez[k] = hx[k] = hy[k] = 0.f;
        eR[k] = eL[k] = false;
        top[k] = bot[k] = srcf[k] = det[k] = false;
        if (idx < ncell) {
            K = k + 1;
            int l = idx / NY;
            int j = idx - l * NY;
            int i = r0 + l;
            off_[k] = idx; jc[k] = j;
            dmp[k] = d_damp1[i] * d_damp1[j];
            iek[k] = d_ie[i * NY + j];
            eR[k] = (j < NY - 1);  eL[k] = (j > 0);
            top[k] = (l == 0);     bot[k] = (l == h - 1);
            if (top[k] && hasA) { spinA = true; dmpH = d_damp1[r0 - 1] * d_damp1[j]; }
            if (top[k] && !hasA) spinA = false;
            if (bot[k] && hasB) spinB = true;
            int p = (j + 10) / 80 - 1;
            int o2 = (j + 10) - 80 * (p + 1);
            bool inport = (p >= 0 && p < 4 && o2 < 20);
            srcf[k] = (i == SRC_I) && inport;
            det[k]  = (i == DET_I) && inport;
            if (srcf[k]) psrc[k] = PI_F * phases[batch * 4 + p];
            if (det[k])  oidx[k] = batch * 80 + p * 20 + o2;
        }
    }
    spinA = spinA && hasA;
    spinB = spinB && hasB;
    __syncthreads();

    const float W = (float)(2.0 * 3.14159265358979323846 * (12.5 / 1550.0));

    for (unsigned t = 1; t <= STEPS; ++t) {
        const int q = (int)((t - 1) & 1u);     // parity of Ez(t-1) buffers
        const int p = (int)(t & 1u);           // parity we publish this step

        // ---- wait for neighbors' step t-1 publish (usually already done) ----
        if (spinA) while (ld_acq(flagA) < t - 1) { }
        if (spinB) while (ld_acq(flagB) < t - 1) { }

        const float* ezA = rdA + q * BND_P;    // Ez(t-1, r0-1, :)
        const float* ezB = rdB + q * BND_P;    // Ez(t-1, r1,   :)

        // ---- H substep (incl. redundant Hy halo row r0-1) ----
        if (spinA && top[0]) {
            hyH = dmpH * (hyH + 0.5f * (ez[0] - ezA[jc[0]]));
        }
        #pragma unroll
        for (int k = 0; k < KMAX; ++k) if (k < K) {
            int o = off_[k];
            float ezc = ez[k];
            float ezR = eR[k] ? sEz[o + 1] : ezc;
            float ezD = bot[k] ? (hasB ? ezB[jc[k]] : ezc) : sEz[o + NY];
            hx[k] = dmp[k] * (hx[k] - 0.5f * (ezR - ezc));
            hy[k] = dmp[k] * (hy[k] + 0.5f * (ezD - ezc));
            sHx[o] = hx[k];
            sHy[o] = hy[k];
        }
        __syncthreads();

        // ---- E substep + publish boundary Ez rows (parity p) ----
        float tf = (float)(t - 1);
        float* wT = wrT + p * BND_P;
        float* wB = wrB + p * BND_P;
        #pragma unroll
        for (int k = 0; k < KMAX; ++k) if (k < K) {
            int o = off_[k];
            float hyU = top[k] ? (hasA ? hyH : hy[k]) : sHy[o - NY];
            float hxL = eL[k] ? sHx[o - 1] : hx[k];
            float e = dmp[k] * (ez[k] + iek[k] * ((hy[k] - hyU) - (hx[k] - hxL)));
            if (srcf[k]) e += sinf(tf * W + psrc[k]);
            ez[k] = e;
            sEz[o] = e;
            if (top[k]) wT[jc[k]] = e;
            if (bot[k]) wB[jc[k]] = e;
        }
        __syncthreads();

        if (tid == 0) {
            __threadfence();
            st_rel(flagS, t);
        }
    }

    // ---- detector: final Ez at row 370 lives in registers ----
    #pragma unroll
    for (int k = 0; k < KMAX; ++k) if (k < K && det[k]) out[oidx[k]] = ez[k];
}

extern "C" void kernel_launch(void* const* d_in, const int* in_sizes, int n_in,
                              void* d_out, int out_size) {
    const float* phases = (const float*)d_in[0];   // (2,4)
    const float* radius = (const float*)d_in[1];   // (8,8)
    float* out = (float*)d_out;                    // (2,4,20)
    int nzero = 2*2*NBLK*NY;                       // largest init range
    setup_kernel<<<(nzero + 255) / 256, 256>>>(radius);
    fdtd_kernel<<<NBLK, TPB>>>(phases, out);
}

// round 4
// speedup vs baseline: 3.2804x; 1.0760x over previous
#include <cuda_runtime.h>
#include <math.h>

#define NX 400
#define NY 400
#define NC (NX*NY)
#define STEPS 300
#define NSTRIP 74
#define NBLK (2*NSTRIP)
#define TPB 1024
#define KMAX 3
#define SRC_I 30
#define DET_I 370
#define PI_F 3.14159265358979323846f
#define BND_P (2*NBLK*NY)      // parity stride in d_bnd

// flag bits per owned cell
#define F_CELL 1u
#define F_ER   2u
#define F_EL   4u
#define F_TOP  8u
#define F_BOT  16u
#define F_SRC  32u

// Persistent device state (no allocations allowed)
__device__ float d_ie[NC];                 // COURANT / eps
__device__ float d_damp1[NX];              // 1-D damp profile (x == y)
__device__ float d_bnd[2*2*NBLK*NY];       // [parity][side:0=top,1=bot][blk][j]
__device__ unsigned d_flag[NBLK*32];       // one 128B line per block

__device__ __forceinline__ unsigned ld_acq(const unsigned* p) {
    unsigned v;
    asm volatile("ld.global.acquire.gpu.u32 %0, [%1];" : "=r"(v) : "l"(p) : "memory");
    return v;
}
__device__ __forceinline__ void st_rel(unsigned* p, unsigned v) {
    asm volatile("st.global.release.gpu.u32 [%0], %1;" :: "l"(p), "r"(v) : "memory");
}

// ---------------- setup: eps, damp, zero boundary buffers, reset flags ----------------
__global__ void setup_kernel(const float* __restrict__ radius) {
    int idx = blockIdx.x * blockDim.x + threadIdx.x;
    if (idx < NBLK*32) d_flag[idx] = 0u;
    if (idx < 2*2*NBLK*NY) d_bnd[idx] = 0.f;
    if (idx < NX) {
        float v = 1.0f;
        if (idx < 10) {
            float rr = (10 - idx - 0.5f) * 0.1f;
            v = expf(-0.5f * rr * rr * rr);
        } else if (idx >= NX - 10) {
            float rr = (10 - (NX - 1 - idx) - 0.5f) * 0.1f;
            v = expf(-0.5f * rr * rr * rr);
        }
        d_damp1[idx] = v;
    }
    if (idx >= NC) return;
    int i = idx / NY;
    int j = idx - i * NY;
    int p   = (j + 10) / 80 - 1;
    int off = (j + 10) - 80 * (p + 1);
    bool inport = (p >= 0 && p < 4 && off < 20);
    float eps = 1.0f;
    if ((i < SRC_I || i >= DET_I) && inport) eps = 2.8f;
    if (i >= 80 && i < 320 && j >= 80 && j < 320) {
        int X = i - 80, Y = j - 80;
        int a = X / 30, b = Y / 30;
        float r = radius[a * 8 + b];
        if (r < 0.3f) r = 0.0f;
        float dx = (float)(X - (15 + 30 * a));
        float dy = (float)(Y - (15 + 30 * b));
        eps = (dx * dx + dy * dy <= r * r) ? 1.0f : 2.8f;
    }
    d_ie[idx] = 0.5f / eps;
}

// ---------------- persistent strip kernel: one-step-lagged neighbor sync ----------------
__global__ void __launch_bounds__(TPB, 1)
fdtd_kernel(const float* __restrict__ phases, float* __restrict__ out)
{
    __shared__ float sEz[6*NY], sHx[6*NY], sHy[6*NY];

    const int bk    = blockIdx.x;
    const int batch = bk / NSTRIP;
    const int s     = bk - batch * NSTRIP;
    const int r0    = (s * NX) / NSTRIP;
    const int r1    = ((s + 1) * NX) / NSTRIP;
    const int h     = r1 - r0;
    const int ncell = h * NY;
    const bool hasA = (s > 0);
    const bool hasB = (s < NSTRIP - 1);
    const int tid   = threadIdx.x;
    const int bkA   = hasA ? bk - 1 : bk;
    const int bkB   = hasB ? bk + 1 : bk;

    for (int x = tid; x < 6*NY; x += TPB) { sEz[x] = 0.f; sHx[x] = 0.f; sHy[x] = 0.f; }

    const unsigned* flagA = &d_flag[bkA * 32];
    const unsigned* flagB = &d_flag[bkB * 32];
    unsigned*       flagS = &d_flag[bk * 32];

    const float* rdA = &d_bnd[1*NBLK*NY + bkA*NY];  // above's bottom Ez row (parity added per step)
    const float* rdB = &d_bnd[0*NBLK*NY + bkB*NY];  // below's top Ez row
    float*       wrT = &d_bnd[0*NBLK*NY + bk*NY];   // own top Ez row
    float*       wrB = &d_bnd[1*NBLK*NY + bk*NY];   // own bottom Ez row

    // Per-thread owned cells (fixed for whole simulation)
    int      jc[KMAX];
    unsigned fl[KMAX];
    float    dmp[KMAX], iek[KMAX], psrc[KMAX];
    float    ez[KMAX], hx[KMAX], hy[KMAX];
    bool  spinA = false, spinB = false;
    float hyH = 0.f, dmpH = 0.f;          // redundant Hy halo at row r0-1 (top threads, k=0)
    #pragma unroll
    for (int k = 0; k < KMAX; ++k) {
        int idx = tid + k * TPB;
        jc[k] = 0; fl[k] = 0u;
        dmp[k] = 0.f; iek[k] = 0.f; psrc[k] = 0.f;
        ez[k] = hx[k] = hy[k] = 0.f;
        if (idx < ncell) {
            int l = idx / NY;
            int j = idx - l * NY;
            int i = r0 + l;
            jc[k] = j;
            dmp[k] = d_damp1[i] * d_damp1[j];
            iek[k] = d_ie[i * NY + j];
            unsigned f = F_CELL;
            if (j < NY - 1) f |= F_ER;
            if (j > 0)      f |= F_EL;
            if (l == 0)     f |= F_TOP;
            if (l == h - 1) f |= F_BOT;
            int p = (j + 10) / 80 - 1;
            int o2 = (j + 10) - 80 * (p + 1);
            bool inport = (p >= 0 && p < 4 && o2 < 20);
            if (i == SRC_I && inport) { f |= F_SRC; psrc[k] = PI_F * phases[batch * 4 + p]; }
            fl[k] = f;
            if (l == 0 && hasA) { spinA = true; dmpH = d_damp1[r0 - 1] * d_damp1[j]; }
            if (l == h - 1 && hasB) spinB = true;
        }
    }
    __syncthreads();

    const float W = (float)(2.0 * 3.14159265358979323846 * (12.5 / 1550.0));
    float tf = 0.f;

    for (unsigned t = 1; t <= STEPS; ++t) {
        const int q = (int)((t - 1) & 1u);     // parity of Ez(t-1) buffers
        const int p = (int)(t & 1u);           // parity we publish this step

        // ---- wait for neighbors' step t-1 publish (usually already done) ----
        if (spinA) while (ld_acq(flagA) < t - 1) { }
        if (spinB) while (ld_acq(flagB) < t - 1) { }

        const float* ezA = rdA + q * BND_P;    // Ez(t-1, r0-1, :)
        const float* ezB = rdB + q * BND_P;    // Ez(t-1, r1,   :)

        // ---- H substep (incl. redundant Hy halo row r0-1) ----
        if (spinA) {
            hyH = dmpH * (hyH + 0.5f * (ez[0] - ezA[jc[0]]));
        }
        #pragma unroll
        for (int k = 0; k < KMAX; ++k) if (fl[k] & F_CELL) {
            int o = tid + k * TPB;
            float ezc = ez[k];
            float ezR = (fl[k] & F_ER)  ? sEz[o + 1] : ezc;
            float ezD = (fl[k] & F_BOT) ? (hasB ? ezB[jc[k]] : ezc) : sEz[o + NY];
            hx[k] = dmp[k] * (hx[k] - 0.5f * (ezR - ezc));
            hy[k] = dmp[k] * (hy[k] + 0.5f * (ezD - ezc));
            sHx[o] = hx[k];
            sHy[o] = hy[k];
        }
        __syncthreads();

        // ---- E substep + publish boundary Ez rows (parity p) ----
        float* wT = wrT + p * BND_P;
        float* wB = wrB + p * BND_P;
        #pragma unroll
        for (int k = 0; k < KMAX; ++k) if (fl[k] & F_CELL) {
            int o = tid + k * TPB;
            float hyU = (fl[k] & F_TOP) ? (hasA ? hyH : hy[k]) : sHy[o - NY];
            float hxL = (fl[k] & F_EL)  ? sHx[o - 1] : hx[k];
            float e = dmp[k] * (ez[k] + iek[k] * ((hy[k] - hyU) - (hx[k] - hxL)));
            if (fl[k] & F_SRC) e += sinf(tf * W + psrc[k]);
            ez[k] = e;
            sEz[o] = e;
            if (fl[k] & F_TOP) wT[jc[k]] = e;
            if (fl[k] & F_BOT) wB[jc[k]] = e;
        }
        __syncthreads();

        if (tid == 0) {
            __threadfence();
            st_rel(flagS, t);
        }
        tf += 1.f;
    }

    // ---- detector: final Ez at row 370 lives in registers ----
    #pragma unroll
    for (int k = 0; k < KMAX; ++k) if (fl[k] & F_CELL) {
        int idx = tid + k * TPB;
        int l = idx / NY;
        int i = r0 + l;
        if (i == DET_I) {
            int j = idx - l * NY;
            int p = (j + 10) / 80 - 1;
            int o2 = (j + 10) - 80 * (p + 1);
            if (p >= 0 && p < 4 && o2 < 20)
                out[batch * 80 + p * 20 + o2] = ez[k];
        }
    }
}

extern "C" void kernel_launch(void* const* d_in, const int* in_sizes, int n_in,
                              void* d_out, int out_size) {
    const float* phases = (const float*)d_in[0];   // (2,4)
    const float* radius = (const float*)d_in[1];   // (8,8)
    float* out = (float*)d_out;                    // (2,4,20)
    int nzero = 2*2*NBLK*NY;                       // largest init range
    setup_kernel<<<(nzero + 255) / 256, 256>>>(radius);
    fdtd_kernel<<<NBLK, TPB>>>(phases, out);
}

// round 5
// speedup vs baseline: 4.4955x; 1.3704x over previous
#include <cuda_runtime.h>
#include <math.h>

#define NX 400
#define NY 400
#define NC (NX*NY)
#define STEPS 300
#define NSTRIP 74
#define NBLK (2*NSTRIP)
#define TPB 640
#define SRC_I 30
#define DET_I 370
#define PI_F 3.14159265358979323846f
#define BND_P (2*NBLK*NY)      // parity stride in d_bnd

// Persistent device state (no allocations allowed)
__device__ float d_ie[NC];                 // COURANT / eps
__device__ float d_damp1[NX];              // 1-D damp profile (x == y)
__device__ float d_bnd[2*2*NBLK*NY];       // [parity][side:0=top,1=bot][blk][j]
__device__ unsigned d_flag[NBLK*32];       // one 128B line per block

__device__ __forceinline__ unsigned ld_acq(const unsigned* p) {
    unsigned v;
    asm volatile("ld.global.acquire.gpu.u32 %0, [%1];" : "=r"(v) : "l"(p) : "memory");
    return v;
}
__device__ __forceinline__ void st_rel(unsigned* p, unsigned v) {
    asm volatile("st.global.release.gpu.u32 [%0], %1;" :: "l"(p), "r"(v) : "memory");
}

// ---------------- setup: eps, damp, zero boundary buffers, reset flags ----------------
__global__ void setup_kernel(const float* __restrict__ radius) {
    int idx = blockIdx.x * blockDim.x + threadIdx.x;
    if (idx < NBLK*32) d_flag[idx] = 0u;
    if (idx < 2*2*NBLK*NY) d_bnd[idx] = 0.f;
    if (idx < NX) {
        float v = 1.0f;
        if (idx < 10) {
            float rr = (10 - idx - 0.5f) * 0.1f;
            v = expf(-0.5f * rr * rr * rr);
        } else if (idx >= NX - 10) {
            float rr = (10 - (NX - 1 - idx) - 0.5f) * 0.1f;
            v = expf(-0.5f * rr * rr * rr);
        }
        d_damp1[idx] = v;
    }
    if (idx >= NC) return;
    int i = idx / NY;
    int j = idx - i * NY;
    int p   = (j + 10) / 80 - 1;
    int off = (j + 10) - 80 * (p + 1);
    bool inport = (p >= 0 && p < 4 && off < 20);
    float eps = 1.0f;
    if ((i < SRC_I || i >= DET_I) && inport) eps = 2.8f;
    if (i >= 80 && i < 320 && j >= 80 && j < 320) {
        int X = i - 80, Y = j - 80;
        int a = X / 30, b = Y / 30;
        float r = radius[a * 8 + b];
        if (r < 0.3f) r = 0.0f;
        float dx = (float)(X - (15 + 30 * a));
        float dy = (float)(Y - (15 + 30 * b));
        eps = (dx * dx + dy * dy <= r * r) ? 1.0f : 2.8f;
    }
    d_ie[idx] = 0.5f / eps;
}

// ---------------- persistent strip kernel: float4 quads, one per thread ----------------
__global__ void __launch_bounds__(TPB, 1)
fdtd_kernel(const float* __restrict__ phases, float* __restrict__ out)
{
    __shared__ float sEz[6*NY];       // Ez of own strip rows (step t-1 during H)
    __shared__ float sHy[6*NY];       // Hy of own strip rows (step t during E)
    __shared__ float sHxL[6*100];     // last element (j = 4*jq+3) of each Hx quad

    const int bk    = blockIdx.x;
    const int batch = bk / NSTRIP;
    const int s     = bk - batch * NSTRIP;
    const int r0    = (s * NX) / NSTRIP;
    const int r1    = ((s + 1) * NX) / NSTRIP;
    const int h     = r1 - r0;
    const bool hasA = (s > 0);
    const bool hasB = (s < NSTRIP - 1);
    const int tid   = threadIdx.x;
    const int bkA   = hasA ? bk - 1 : bk;
    const int bkB   = hasB ? bk + 1 : bk;

    const int  l    = tid / 100;
    const int  jq   = tid - l * 100;
    const bool act  = (tid < h * 100);
    const int  i    = r0 + l;
    const int  j0   = jq * 4;
    const int  o    = l * NY + j0;
    const bool topT = act && (l == 0);
    const bool botT = act && (l == h - 1);
    const bool spinA = topT && hasA;
    const bool spinB = botT && hasB;

    for (int x = tid; x < 6*NY; x += TPB) { sEz[x] = 0.f; sHy[x] = 0.f; }
    for (int x = tid; x < 6*100; x += TPB) sHxL[x] = 0.f;

    const unsigned* flagA = &d_flag[bkA * 32];
    const unsigned* flagB = &d_flag[bkB * 32];
    unsigned*       flagS = &d_flag[bk * 32];

    const float* rdA = &d_bnd[1*NBLK*NY + bkA*NY + j0];  // above's bottom Ez row quad
    const float* rdB = &d_bnd[0*NBLK*NY + bkB*NY + j0];  // below's top Ez row quad
    float*       wrT = &d_bnd[0*NBLK*NY + bk*NY + j0];
    float*       wrB = &d_bnd[1*NBLK*NY + bk*NY + j0];

    // per-thread constant and state quads
    float4 ez = {0,0,0,0}, hx = {0,0,0,0}, hy = {0,0,0,0};
    float4 dmp = {0,0,0,0}, iek = {0,0,0,0}, dmpH = {0,0,0,0};
    float4 hyH = {0,0,0,0};
    float4 srcm = {0,0,0,0}, Ssin = {0,0,0,0}, Scos = {0,0,0,0};
    bool hasSrc = false, hasDet = false;

    if (act) {
        float di = d_damp1[i];
        dmp.x = di * d_damp1[j0];   dmp.y = di * d_damp1[j0+1];
        dmp.z = di * d_damp1[j0+2]; dmp.w = di * d_damp1[j0+3];
        iek = *(const float4*)&d_ie[i * NY + j0];
        if (spinA) {
            float dh = d_damp1[r0 - 1];
            dmpH.x = dh * d_damp1[j0];   dmpH.y = dh * d_damp1[j0+1];
            dmpH.z = dh * d_damp1[j0+2]; dmpH.w = dh * d_damp1[j0+3];
        }
        if (i == SRC_I || i == DET_I) {
            float* sm = &srcm.x; float* ss = &Ssin.x; float* sc = &Scos.x;
            #pragma unroll
            for (int c = 0; c < 4; ++c) {
                int j = j0 + c;
                int p = (j + 10) / 80 - 1;
                int o2 = (j + 10) - 80 * (p + 1);
                bool inport = (p >= 0 && p < 4 && o2 < 20);
                if (inport && i == SRC_I) {
                    sm[c] = 1.f;
                    float ps = PI_F * phases[batch * 4 + p];
                    ss[c] = sinf(ps);     // angle at t=1 (tf=0)
                    sc[c] = cosf(ps);
                    hasSrc = true;
                }
                if (inport && i == DET_I) hasDet = true;
            }
        }
    }
    const float W  = (float)(2.0 * 3.14159265358979323846 * (12.5 / 1550.0));
    const float cW = cosf(W), sW = sinf(W);
    __syncthreads();

    for (unsigned t = 1; t <= STEPS; ++t) {
        const int q = (int)((t - 1) & 1u);
        const int p = (int)(t & 1u);

        // ---- wait for neighbors' step t-1 publish (usually already done) ----
        if (spinA) while (ld_acq(flagA) < t - 1) { }
        if (spinB) while (ld_acq(flagB) < t - 1) { }

        // ---- H substep ----
        if (act) {
            if (spinA) {                       // redundant Hy halo row r0-1
                float4 ezA = *(const float4*)(rdA + q * BND_P);
                hyH.x = dmpH.x * (hyH.x + 0.5f * (ez.x - ezA.x));
                hyH.y = dmpH.y * (hyH.y + 0.5f * (ez.y - ezA.y));
                hyH.z = dmpH.z * (hyH.z + 0.5f * (ez.z - ezA.z));
                hyH.w = dmpH.w * (hyH.w + 0.5f * (ez.w - ezA.w));
            }
            float4 ezD;
            if (botT) ezD = hasB ? *(const float4*)(rdB + q * BND_P) : ez;
            else      ezD = *(const float4*)&sEz[o + NY];
            float ezE = (jq < 99) ? sEz[o + 4] : ez.w;       // j=399 edge -> diff 0

            hx.x = dmp.x * (hx.x - 0.5f * (ez.y - ez.x));
            hx.y = dmp.y * (hx.y - 0.5f * (ez.z - ez.y));
            hx.z = dmp.z * (hx.z - 0.5f * (ez.w - ez.z));
            hx.w = dmp.w * (hx.w - 0.5f * (ezE  - ez.w));
            hy.x = dmp.x * (hy.x + 0.5f * (ezD.x - ez.x));
            hy.y = dmp.y * (hy.y + 0.5f * (ezD.y - ez.y));
            hy.z = dmp.z * (hy.z + 0.5f * (ezD.z - ez.z));
            hy.w = dmp.w * (hy.w + 0.5f * (ezD.w - ez.w));

            *(float4*)&sHy[o] = hy;
            sHxL[l * 100 + jq] = hx.w;
        }
        __syncthreads();

        // ---- E substep + publish boundary Ez rows (parity p) ----
        if (act) {
            float4 hyU = topT ? (hasA ? hyH : hy) : *(const float4*)&sHy[o - NY];
            float hxW  = (jq > 0) ? sHxL[l * 100 + jq - 1] : hx.x;   // j=0 edge -> diff 0

            ez.x = dmp.x * (ez.x + iek.x * ((hy.x - hyU.x) - (hx.x - hxW)));
            ez.y = dmp.y * (ez.y + iek.y * ((hy.y - hyU.y) - (hx.y - hx.x)));
            ez.z = dmp.z * (ez.z + iek.z * ((hy.z - hyU.z) - (hx.z - hx.y)));
            ez.w = dmp.w * (ez.w + iek.w * ((hy.w - hyU.w) - (hx.w - hx.z)));

            if (hasSrc) {
                ez.x += srcm.x * Ssin.x;  ez.y += srcm.y * Ssin.y;
                ez.z += srcm.z * Ssin.z;  ez.w += srcm.w * Ssin.w;
                float ns, nc;
                ns = Ssin.x * cW + Scos.x * sW; nc = Scos.x * cW - Ssin.x * sW; Ssin.x = ns; Scos.x = nc;
                ns = Ssin.y * cW + Scos.y * sW; nc = Scos.y * cW - Ssin.y * sW; Ssin.y = ns; Scos.y = nc;
                ns = Ssin.z * cW + Scos.z * sW; nc = Scos.z * cW - Ssin.z * sW; Ssin.z = ns; Scos.z = nc;
                ns = Ssin.w * cW + Scos.w * sW; nc = Scos.w * cW - Ssin.w * sW; Ssin.w = ns; Scos.w = nc;
            }

            *(float4*)&sEz[o] = ez;
            if (topT) *(float4*)(wrT + p * BND_P) = ez;
            if (botT) *(float4*)(wrB + p * BND_P) = ez;
        }
        __syncthreads();

        if (tid == 0) {
            __threadfence();
            st_rel(flagS, t);
        }
    }

    // ---- detector: final Ez at row 370 lives in registers ----
    if (hasDet) {
        const float* ec = &ez.x;
        #pragma unroll
        for (int c = 0; c < 4; ++c) {
            int j = j0 + c;
            int p = (j + 10) / 80 - 1;
            int o2 = (j + 10) - 80 * (p + 1);
            if (p >= 0 && p < 4 && o2 < 20)
                out[batch * 80 + p * 20 + o2] = ec[c];
        }
    }
}

extern "C" void kernel_launch(void* const* d_in, const int* in_sizes, int n_in,
                              void* d_out, int out_size) {
    const float* phases = (const float*)d_in[0];   // (2,4)
    const float* radius = (const float*)d_in[1];   // (8,8)
    float* out = (float*)d_out;                    // (2,4,20)
    int nzero = 2*2*NBLK*NY;                       // largest init range
    setup_kernel<<<(nzero + 255) / 256, 256>>>(radius);
    fdtd_kernel<<<NBLK, TPB>>>(phases, out);
}

// round 6
// speedup vs baseline: 5.1748x; 1.1511x over previous
#include <cuda_runtime.h>
#include <math.h>

#define NX 400
#define NY 400
#define NC (NX*NY)
#define STEPS 300
#define NSTRIP 74
#define NBLK (2*NSTRIP)
#define TPB 640
#define SRC_I 30
#define DET_I 370
#define PI_F 3.14159265358979323846f
#define BND_P (2*NBLK*NY)      // parity stride in d_bnd

// Persistent device state (no allocations allowed)
__device__ float d_ie[NC];                 // COURANT / eps
__device__ float d_damp1[NX];              // 1-D damp profile (x == y)
__device__ float d_bnd[2*2*NBLK*NY];       // [parity][side:0=top,1=bot][blk][j]
__device__ unsigned d_flagT[NBLK*32];      // top-row publish counters (1 line/blk)
__device__ unsigned d_flagB[NBLK*32];      // bottom-row publish counters

__device__ __forceinline__ unsigned ld_acq(const unsigned* p) {
    unsigned v;
    asm volatile("ld.global.acquire.gpu.u32 %0, [%1];" : "=r"(v) : "l"(p) : "memory");
    return v;
}
__device__ __forceinline__ void red_rel_add(unsigned* p, unsigned v) {
    asm volatile("red.release.gpu.global.add.u32 [%0], %1;" :: "l"(p), "r"(v) : "memory");
}

// ---------------- setup: eps, damp, zero boundary buffers, reset flags ----------------
__global__ void setup_kernel(const float* __restrict__ radius) {
    int idx = blockIdx.x * blockDim.x + threadIdx.x;
    if (idx < NBLK*32) { d_flagT[idx] = 0u; d_flagB[idx] = 0u; }
    if (idx < 2*2*NBLK*NY) d_bnd[idx] = 0.f;
    if (idx < NX) {
        float v = 1.0f;
        if (idx < 10) {
            float rr = (10 - idx - 0.5f) * 0.1f;
            v = expf(-0.5f * rr * rr * rr);
        } else if (idx >= NX - 10) {
            float rr = (10 - (NX - 1 - idx) - 0.5f) * 0.1f;
            v = expf(-0.5f * rr * rr * rr);
        }
        d_damp1[idx] = v;
    }
    if (idx >= NC) return;
    int i = idx / NY;
    int j = idx - i * NY;
    int p   = (j + 10) / 80 - 1;
    int off = (j + 10) - 80 * (p + 1);
    bool inport = (p >= 0 && p < 4 && off < 20);
    float eps = 1.0f;
    if ((i < SRC_I || i >= DET_I) && inport) eps = 2.8f;
    if (i >= 80 && i < 320 && j >= 80 && j < 320) {
        int X = i - 80, Y = j - 80;
        int a = X / 30, b = Y / 30;
        float r = radius[a * 8 + b];
        if (r < 0.3f) r = 0.0f;
        float dx = (float)(X - (15 + 30 * a));
        float dy = (float)(Y - (15 + 30 * b));
        eps = (dx * dx + dy * dy <= r * r) ? 1.0f : 2.8f;
    }
    d_ie[idx] = 0.5f / eps;
}

// ---------------- persistent strip kernel: quads + early per-thread release publish ----------------
__global__ void __launch_bounds__(TPB, 1)
fdtd_kernel(const float* __restrict__ phases, float* __restrict__ out)
{
    __shared__ float sEz[6*NY];       // Ez of own strip rows
    __shared__ float sHy[6*NY];       // Hy of own strip rows
    __shared__ float sHxL[6*100];     // last element (j = 4*jq+3) of each Hx quad

    const int bk    = blockIdx.x;
    const int batch = bk / NSTRIP;
    const int s     = bk - batch * NSTRIP;
    const int r0    = (s * NX) / NSTRIP;
    const int r1    = ((s + 1) * NX) / NSTRIP;
    const int h     = r1 - r0;
    const bool hasA = (s > 0);
    const bool hasB = (s < NSTRIP - 1);
    const int tid   = threadIdx.x;
    const int bkA   = hasA ? bk - 1 : bk;
    const int bkB   = hasB ? bk + 1 : bk;

    const int  l    = tid / 100;
    const int  jq   = tid - l * 100;
    const bool act  = (tid < h * 100);
    const int  i    = r0 + l;
    const int  j0   = jq * 4;
    const int  o    = l * NY + j0;
    const bool topT = act && (l == 0);
    const bool botT = act && (l == h - 1);
    const bool spinA = topT && hasA;
    const bool spinB = botT && hasB;

    for (int x = tid; x < 6*NY; x += TPB) { sEz[x] = 0.f; sHy[x] = 0.f; }
    for (int x = tid; x < 6*100; x += TPB) sHxL[x] = 0.f;

    const unsigned* flagA = &d_flagB[bkA * 32];   // above's bottom publish
    const unsigned* flagBp = &d_flagT[bkB * 32];  // below's top publish
    unsigned* myFT = &d_flagT[bk * 32];
    unsigned* myFB = &d_flagB[bk * 32];

    const float* rdA = &d_bnd[1*NBLK*NY + bkA*NY + j0];  // above's bottom Ez row quad
    const float* rdB = &d_bnd[0*NBLK*NY + bkB*NY + j0];  // below's top Ez row quad
    float*       wrT = &d_bnd[0*NBLK*NY + bk*NY + j0];
    float*       wrB = &d_bnd[1*NBLK*NY + bk*NY + j0];

    // per-thread constant and state quads
    float4 ez = {0,0,0,0}, hx = {0,0,0,0}, hy = {0,0,0,0};
    float4 dmp = {0,0,0,0}, iek = {0,0,0,0}, dmpH = {0,0,0,0};
    float4 hyH = {0,0,0,0};
    float4 srcm = {0,0,0,0}, Ssin = {0,0,0,0}, Scos = {0,0,0,0};
    bool hasSrc = false, hasDet = false;

    if (act) {
        float di = d_damp1[i];
        dmp.x = di * d_damp1[j0];   dmp.y = di * d_damp1[j0+1];
        dmp.z = di * d_damp1[j0+2]; dmp.w = di * d_damp1[j0+3];
        iek = *(const float4*)&d_ie[i * NY + j0];
        if (spinA) {
            float dh = d_damp1[r0 - 1];
            dmpH.x = dh * d_damp1[j0];   dmpH.y = dh * d_damp1[j0+1];
            dmpH.z = dh * d_damp1[j0+2]; dmpH.w = dh * d_damp1[j0+3];
        }
        if (i == SRC_I || i == DET_I) {
            float* sm = &srcm.x; float* ss = &Ssin.x; float* sc = &Scos.x;
            #pragma unroll
            for (int c = 0; c < 4; ++c) {
                int j = j0 + c;
                int p = (j + 10) / 80 - 1;
                int o2 = (j + 10) - 80 * (p + 1);
                bool inport = (p >= 0 && p < 4 && o2 < 20);
                if (inport && i == SRC_I) {
                    sm[c] = 1.f;
                    float ps = PI_F * phases[batch * 4 + p];
                    ss[c] = sinf(ps);     // angle at t=1 (tf=0)
                    sc[c] = cosf(ps);
                    hasSrc = true;
                }
                if (inport && i == DET_I) hasDet = true;
            }
        }
    }
    const float W  = (float)(2.0 * 3.14159265358979323846 * (12.5 / 1550.0));
    const float cW = cosf(W), sW = sinf(W);
    __syncthreads();

    for (unsigned t = 1; t <= STEPS; ++t) {
        const int q = (int)((t - 1) & 1u);
        const int p = (int)(t & 1u);
        const unsigned thr = 100u * (t - 1u);

        // ---- prefetch own-smem H operands (valid since last bar), overlap with spin ----
        float ezE = ez.w;
        float4 ezDs = ez;
        if (act) {
            if (jq < 99) ezE = sEz[o + 4];
            if (!botT)   ezDs = *(const float4*)&sEz[o + NY];
        }

        // ---- wait for neighbors' step t-1 publish (usually already done) ----
        if (spinA) while (ld_acq(flagA) < thr) { }
        if (spinB) while (ld_acq(flagBp) < thr) { }

        // ---- H substep ----
        if (act) {
            if (spinA) {                       // redundant Hy halo row r0-1
                float4 ezA = *(const float4*)(rdA + q * BND_P);
                hyH.x = dmpH.x * (hyH.x + 0.5f * (ez.x - ezA.x));
                hyH.y = dmpH.y * (hyH.y + 0.5f * (ez.y - ezA.y));
                hyH.z = dmpH.z * (hyH.z + 0.5f * (ez.z - ezA.z));
                hyH.w = dmpH.w * (hyH.w + 0.5f * (ez.w - ezA.w));
            }
            float4 ezD = ezDs;
            if (spinB) ezD = *(const float4*)(rdB + q * BND_P);

            hx.x = dmp.x * (hx.x - 0.5f * (ez.y - ez.x));
            hx.y = dmp.y * (hx.y - 0.5f * (ez.z - ez.y));
            hx.z = dmp.z * (hx.z - 0.5f * (ez.w - ez.z));
            hx.w = dmp.w * (hx.w - 0.5f * (ezE  - ez.w));
            hy.x = dmp.x * (hy.x + 0.5f * (ezD.x - ez.x));
            hy.y = dmp.y * (hy.y + 0.5f * (ezD.y - ez.y));
            hy.z = dmp.z * (hy.z + 0.5f * (ezD.z - ez.z));
            hy.w = dmp.w * (hy.w + 0.5f * (ezD.w - ez.w));

            *(float4*)&sHy[o] = hy;
            sHxL[l * 100 + jq] = hx.w;
        }
        __syncthreads();

        // ---- E substep; boundary threads publish + release-flag EARLY ----
        if (act) {
            float4 hyU = topT ? (hasA ? hyH : hy) : *(const float4*)&sHy[o - NY];
            float hxW  = (jq > 0) ? sHxL[l * 100 + jq - 1] : hx.x;   // j=0 edge -> diff 0

            ez.x = dmp.x * (ez.x + iek.x * ((hy.x - hyU.x) - (hx.x - hxW)));
            ez.y = dmp.y * (ez.y + iek.y * ((hy.y - hyU.y) - (hx.y - hx.x)));
            ez.z = dmp.z * (ez.z + iek.z * ((hy.z - hyU.z) - (hx.z - hx.y)));
            ez.w = dmp.w * (ez.w + iek.w * ((hy.w - hyU.w) - (hx.w - hx.z)));

            if (hasSrc) {
                ez.x += srcm.x * Ssin.x;  ez.y += srcm.y * Ssin.y;
                ez.z += srcm.z * Ssin.z;  ez.w += srcm.w * Ssin.w;
                float ns, nc;
                ns = Ssin.x * cW + Scos.x * sW; nc = Scos.x * cW - Ssin.x * sW; Ssin.x = ns; Scos.x = nc;
                ns = Ssin.y * cW + Scos.y * sW; nc = Scos.y * cW - Ssin.y * sW; Ssin.y = ns; Scos.y = nc;
                ns = Ssin.z * cW + Scos.z * sW; nc = Scos.z * cW - Ssin.z * sW; Ssin.z = ns; Scos.z = nc;
                ns = Ssin.w * cW + Scos.w * sW; nc = Scos.w * cW - Ssin.w * sW; Ssin.w = ns; Scos.w = nc;
            }

            // publish boundary quads + counter ASAP (per-thread release)
            if (topT) {
                *(float4*)(wrT + p * BND_P) = ez;
                red_rel_add(myFT, 1u);
            }
            if (botT) {
                *(float4*)(wrB + p * BND_P) = ez;
                red_rel_add(myFB, 1u);
            }
            *(float4*)&sEz[o] = ez;
        }
        __syncthreads();
    }

    // ---- detector: final Ez at row 370 lives in registers ----
    if (hasDet) {
        const float* ec = &ez.x;
        #pragma unroll
        for (int c = 0; c < 4; ++c) {
            int j = j0 + c;
            int p = (j + 10) / 80 - 1;
            int o2 = (j + 10) - 80 * (p + 1);
            if (p >= 0 && p < 4 && o2 < 20)
                out[batch * 80 + p * 20 + o2] = ec[c];
        }
    }
}

extern "C" void kernel_launch(void* const* d_in, const int* in_sizes, int n_in,
                              void* d_out, int out_size) {
    const float* phases = (const float*)d_in[0];   // (2,4)
    const float* radius = (const float*)d_in[1];   // (8,8)
    float* out = (float*)d_out;                    // (2,4,20)
    int nzero = 2*2*NBLK*NY;                       // largest init range
    setup_kernel<<<(nzero + 255) / 256, 256>>>(radius);
    fdtd_kernel<<<NBLK, TPB>>>(phases, out);
}

// round 7
// speedup vs baseline: 5.2152x; 1.0078x over previous
#include <cuda_runtime.h>
#include <math.h>

#define NX 400
#define NY 400
#define NC (NX*NY)
#define STEPS 300
#define NSTRIP 74
#define NBLK (2*NSTRIP)
#define TPB 640
#define SRC_I 30
#define DET_I 370
#define PI_F 3.14159265358979323846f
#define BND_P (2*NBLK*NY)      // parity stride in d_bnd

// Persistent device state (no allocations allowed)
__device__ float d_ie[NC];                 // COURANT / eps
__device__ float d_damp1[NX];              // 1-D damp profile (x == y)
__device__ float d_bnd[2*2*NBLK*NY];       // [parity][side:0=top,1=bot][blk][j]
__device__ unsigned d_flagT[NBLK*32];      // top-row publish counters (1 line/blk)
__device__ unsigned d_flagB[NBLK*32];      // bottom-row publish counters

__device__ __forceinline__ unsigned ld_acq(const unsigned* p) {
    unsigned v;
    asm volatile("ld.global.acquire.gpu.u32 %0, [%1];" : "=r"(v) : "l"(p) : "memory");
    return v;
}
__device__ __forceinline__ void red_rel_add(unsigned* p, unsigned v) {
    asm volatile("red.release.gpu.global.add.u32 [%0], %1;" :: "l"(p), "r"(v) : "memory");
}

// ---------------- setup: eps, damp, zero boundary buffers, reset flags ----------------
__global__ void setup_kernel(const float* __restrict__ radius) {
    int idx = blockIdx.x * blockDim.x + threadIdx.x;
    if (idx < NBLK*32) { d_flagT[idx] = 0u; d_flagB[idx] = 0u; }
    if (idx < 2*2*NBLK*NY) d_bnd[idx] = 0.f;
    if (idx < NX) {
        float v = 1.0f;
        if (idx < 10) {
            float rr = (10 - idx - 0.5f) * 0.1f;
            v = expf(-0.5f * rr * rr * rr);
        } else if (idx >= NX - 10) {
            float rr = (10 - (NX - 1 - idx) - 0.5f) * 0.1f;
            v = expf(-0.5f * rr * rr * rr);
        }
        d_damp1[idx] = v;
    }
    if (idx >= NC) return;
    int i = idx / NY;
    int j = idx - i * NY;
    int p   = (j + 10) / 80 - 1;
    int off = (j + 10) - 80 * (p + 1);
    bool inport = (p >= 0 && p < 4 && off < 20);
    float eps = 1.0f;
    if ((i < SRC_I || i >= DET_I) && inport) eps = 2.8f;
    if (i >= 80 && i < 320 && j >= 80 && j < 320) {
        int X = i - 80, Y = j - 80;
        int a = X / 30, b = Y / 30;
        float r = radius[a * 8 + b];
        if (r < 0.3f) r = 0.0f;
        float dx = (float)(X - (15 + 30 * a));
        float dy = (float)(Y - (15 + 30 * b));
        eps = (dx * dx + dy * dy <= r * r) ? 1.0f : 2.8f;
    }
    d_ie[idx] = 0.5f / eps;
}

// ---------- persistent strip kernel: quads, register halos, ONE bar/step ----------
__global__ void __launch_bounds__(TPB, 1)
fdtd_kernel(const float* __restrict__ phases, float* __restrict__ out)
{
    __shared__ float sEz[2*6*NY];     // parity double-buffered Ez of own strip rows

    const int bk    = blockIdx.x;
    const int batch = bk / NSTRIP;
    const int s     = bk - batch * NSTRIP;
    const int r0    = (s * NX) / NSTRIP;
    const int r1    = ((s + 1) * NX) / NSTRIP;
    const int h     = r1 - r0;
    const bool hasA = (s > 0);
    const bool hasB = (s < NSTRIP - 1);
    const int tid   = threadIdx.x;
    const int bkA   = hasA ? bk - 1 : bk;
    const int bkB   = hasB ? bk + 1 : bk;

    const int  l    = tid / 100;
    const int  jq   = tid - l * 100;
    const bool act  = (tid < h * 100);
    const int  i    = r0 + l;
    const int  j0   = jq * 4;
    const int  o    = l * NY + j0;
    const bool topT = act && (l == 0);
    const bool botT = act && (l == h - 1);
    const bool spinA = topT && hasA;
    const bool spinB = botT && hasB;
    const bool upReg  = act && (l > 0);       // up Ez quad comes from smem
    const bool dnReg  = act && (l < h - 1);   // down Ez quad comes from smem

    for (int x = tid; x < 2*6*NY; x += TPB) sEz[x] = 0.f;

    const unsigned* flagA  = &d_flagB[bkA * 32];  // above's bottom publish
    const unsigned* flagBp = &d_flagT[bkB * 32];  // below's top publish
    unsigned* myFT = &d_flagT[bk * 32];
    unsigned* myFB = &d_flagB[bk * 32];

    const float* rdA = &d_bnd[1*NBLK*NY + bkA*NY + j0];  // above's bottom Ez row quad
    const float* rdB = &d_bnd[0*NBLK*NY + bkB*NY + j0];  // below's top Ez row quad
    float*       wrT = &d_bnd[0*NBLK*NY + bk*NY + j0];
    float*       wrB = &d_bnd[1*NBLK*NY + bk*NY + j0];

    // per-thread state
    float4 ez = {0,0,0,0}, hx = {0,0,0,0}, hy = {0,0,0,0}, hyU = {0,0,0,0};
    float4 dmp = {0,0,0,0}, iek = {0,0,0,0};
    float  hxW = 0.f, rU = 1.f, rL = 1.f;      // damp ratios for halo rows
    float4 Ssin = {0,0,0,0}, Scos = {0,0,0,0};
    bool hasSrc = false, hasDet = false;
    const bool edgeTop = topT && !hasA;        // global i==0
    const bool edgeL   = (jq == 0);

    if (act) {
        float di = d_damp1[i];
        dmp.x = di * d_damp1[j0];   dmp.y = di * d_damp1[j0+1];
        dmp.z = di * d_damp1[j0+2]; dmp.w = di * d_damp1[j0+3];
        iek = *(const float4*)&d_ie[i * NY + j0];
        if (i > 0)  rU = d_damp1[i - 1] / di;
        if (j0 > 0) rL = d_damp1[j0 - 1] / d_damp1[j0];
        if (i == SRC_I || i == DET_I) {
            float* ss = &Ssin.x; float* sc = &Scos.x;
            #pragma unroll
            for (int c = 0; c < 4; ++c) {
                int j = j0 + c;
                int p = (j + 10) / 80 - 1;
                int o2 = (j + 10) - 80 * (p + 1);
                bool inport = (p >= 0 && p < 4 && o2 < 20);
                if (inport && i == SRC_I) {
                    float ps = PI_F * phases[batch * 4 + p];
                    ss[c] = sinf(ps);     // angle at t=1 (tf=0)
                    sc[c] = cosf(ps);
                    hasSrc = true;
                }
                if (inport && i == DET_I) hasDet = true;
            }
        }
    }
    const float W  = (float)(2.0 * 3.14159265358979323846 * (12.5 / 1550.0));
    const float cW = cosf(W), sW = sinf(W);
    __syncthreads();

    for (unsigned t = 1; t <= STEPS; ++t) {
        const int q = (int)((t - 1) & 1u);
        const int p = (int)(t & 1u);
        const unsigned thr = 100u * (t - 1u);
        const float* bufQ = sEz + q * (6*NY);
        float*       bufP = sEz + p * (6*NY);

        // ---- gather Ez(t-1) neighbors (smem first; overlap latency with spins) ----
        float  ezL = ez.x, ezE = ez.w;
        float4 ezU = ez,   ezD = ez;
        if (act) {
            if (!edgeL)   ezL = bufQ[o - 1];
            if (jq < 99)  ezE = bufQ[o + 4];
            if (upReg)    ezU = *(const float4*)&bufQ[o - NY];
            if (dnReg)    ezD = *(const float4*)&bufQ[o + NY];
        }
        if (spinA) {
            while (ld_acq(flagA) < thr) { }
            ezU = *(const float4*)(rdA + q * BND_P);
        }
        if (spinB) {
            while (ld_acq(flagBp) < thr) { }
            ezD = *(const float4*)(rdB + q * BND_P);
        }

        if (act) {
            // ---- halo H recurrences (use Ez(t-1)) ----
            hyU.x = rU * dmp.x * (hyU.x + 0.5f * (ez.x - ezU.x));
            hyU.y = rU * dmp.y * (hyU.y + 0.5f * (ez.y - ezU.y));
            hyU.z = rU * dmp.z * (hyU.z + 0.5f * (ez.z - ezU.z));
            hyU.w = rU * dmp.w * (hyU.w + 0.5f * (ez.w - ezU.w));
            hxW   = rL * dmp.x * (hxW   - 0.5f * (ez.x - ezL));

            // ---- own H ----
            hx.x = dmp.x * (hx.x - 0.5f * (ez.y - ez.x));
            hx.y = dmp.y * (hx.y - 0.5f * (ez.z - ez.y));
            hx.z = dmp.z * (hx.z - 0.5f * (ez.w - ez.z));
            hx.w = dmp.w * (hx.w - 0.5f * (ezE  - ez.w));
            hy.x = dmp.x * (hy.x + 0.5f * (ezD.x - ez.x));
            hy.y = dmp.y * (hy.y + 0.5f * (ezD.y - ez.y));
            hy.z = dmp.z * (hy.z + 0.5f * (ezD.z - ez.z));
            hy.w = dmp.w * (hy.w + 0.5f * (ezD.w - ez.w));

            // ---- E: all registers ----
            float4 hyUe = edgeTop ? hy : hyU;      // i==0: dHy_x = 0
            float  hxWe = edgeL   ? hx.x : hxW;    // j==0: dHx_y = 0
            ez.x = dmp.x * (ez.x + iek.x * ((hy.x - hyUe.x) - (hx.x - hxWe)));
            ez.y = dmp.y * (ez.y + iek.y * ((hy.y - hyUe.y) - (hx.y - hx.x)));
            ez.z = dmp.z * (ez.z + iek.z * ((hy.z - hyUe.z) - (hx.z - hx.y)));
            ez.w = dmp.w * (ez.w + iek.w * ((hy.w - hyUe.w) - (hx.w - hx.z)));

            if (hasSrc) {
                ez.x += Ssin.x;  ez.y += Ssin.y;  ez.z += Ssin.z;  ez.w += Ssin.w;
                float ns, nc;
                ns = Ssin.x * cW + Scos.x * sW; nc = Scos.x * cW - Ssin.x * sW; Ssin.x = ns; Scos.x = nc;
                ns = Ssin.y * cW + Scos.y * sW; nc = Scos.y * cW - Ssin.y * sW; Ssin.y = ns; Scos.y = nc;
                ns = Ssin.z * cW + Scos.z * sW; nc = Scos.z * cW - Ssin.z * sW; Ssin.z = ns; Scos.z = nc;
                ns = Ssin.w * cW + Scos.w * sW; nc = Scos.w * cW - Ssin.w * sW; Ssin.w = ns; Scos.w = nc;
            }

            // publish boundary quads + counters ASAP (per-thread release)
            if (topT) {
                *(float4*)(wrT + p * BND_P) = ez;
                red_rel_add(myFT, 1u);
            }
            if (botT) {
                *(float4*)(wrB + p * BND_P) = ez;
                red_rel_add(myFB, 1u);
            }
            *(float4*)&bufP[o] = ez;
        }
        __syncthreads();
    }

    // ---- detector: final Ez at row 370 lives in registers ----
    if (hasDet) {
        const float* ec = &ez.x;
        #pragma unroll
        for (int c = 0; c < 4; ++c) {
            int j = j0 + c;
            int p = (j + 10) / 80 - 1;
            int o2 = (j + 10) - 80 * (p + 1);
            if (p >= 0 && p < 4 && o2 < 20)
                out[batch * 80 + p * 20 + o2] = ec[c];
        }
    }
}

extern "C" void kernel_launch(void* const* d_in, const int* in_sizes, int n_in,
                              void* d_out, int out_size) {
    const float* phases = (const float*)d_in[0];   // (2,4)
    const float* radius = (const float*)d_in[1];   // (8,8)
    float* out = (float*)d_out;                    // (2,4,20)
    int nzero = 2*2*NBLK*NY;                       // largest init range
    setup_kernel<<<(nzero + 255) / 256, 256>>>(radius);
    fdtd_kernel<<<NBLK, TPB>>>(phases, out);
}

// round 8
// speedup vs baseline: 6.6478x; 1.2747x over previous
#include <cuda_runtime.h>
#include <math.h>

#define NX 400
#define NY 400
#define NC (NX*NY)
#define STEPS 300
#define NSTRIP 74
#define NBLK (2*NSTRIP)
#define TPB 640
#define SRC_I 30
#define DET_I 370
#define PI_F 3.14159265358979323846f
#define NSLOT 200                  // 2 columns per 16B slot

// Persistent device state (no allocations allowed)
__device__ float d_ie[NC];                 // COURANT / eps
__device__ float d_damp1[NX];              // 1-D damp profile (x == y)
__device__ float4 d_slT[2*NBLK*NSLOT];     // [parity][blk][slot]: top-row Ez, tag-fused
__device__ float4 d_slB[2*NBLK*NSLOT];     // bottom-row Ez, tag-fused

__device__ __forceinline__ float4 ld_vol_v4(const float4* p) {
    float4 v;
    asm volatile("ld.volatile.global.v4.f32 {%0,%1,%2,%3}, [%4];"
                 : "=f"(v.x), "=f"(v.y), "=f"(v.z), "=f"(v.w) : "l"(p) : "memory");
    return v;
}
__device__ __forceinline__ void st_vol_v4(float4* p, float4 v) {
    asm volatile("st.volatile.global.v4.f32 [%0], {%1,%2,%3,%4};"
                 :: "l"(p), "f"(v.x), "f"(v.y), "f"(v.z), "f"(v.w) : "memory");
}

// ---------------- setup: eps, damp, zero slot buffers ----------------
__global__ void setup_kernel(const float* __restrict__ radius) {
    int idx = blockIdx.x * blockDim.x + threadIdx.x;
    if (idx < 2*NBLK*NSLOT) {
        d_slT[idx] = make_float4(0.f, 0.f, 0.f, 0.f);   // tag 0 == "step 0 published", Ez=0
        d_slB[idx] = make_float4(0.f, 0.f, 0.f, 0.f);
    }
    if (idx < NX) {
        float v = 1.0f;
        if (idx < 10) {
            float rr = (10 - idx - 0.5f) * 0.1f;
            v = expf(-0.5f * rr * rr * rr);
        } else if (idx >= NX - 10) {
            float rr = (10 - (NX - 1 - idx) - 0.5f) * 0.1f;
            v = expf(-0.5f * rr * rr * rr);
        }
        d_damp1[idx] = v;
    }
    if (idx >= NC) return;
    int i = idx / NY;
    int j = idx - i * NY;
    int p   = (j + 10) / 80 - 1;
    int off = (j + 10) - 80 * (p + 1);
    bool inport = (p >= 0 && p < 4 && off < 20);
    float eps = 1.0f;
    if ((i < SRC_I || i >= DET_I) && inport) eps = 2.8f;
    if (i >= 80 && i < 320 && j >= 80 && j < 320) {
        int X = i - 80, Y = j - 80;
        int a = X / 30, b = Y / 30;
        float r = radius[a * 8 + b];
        if (r < 0.3f) r = 0.0f;
        float dx = (float)(X - (15 + 30 * a));
        float dy = (float)(Y - (15 + 30 * b));
        eps = (dx * dx + dy * dy <= r * r) ? 1.0f : 2.8f;
    }
    d_ie[idx] = 0.5f / eps;
}

// ---------- persistent strip kernel: quads, register halos, tag-fused exchange ----------
__global__ void __launch_bounds__(TPB, 1)
fdtd_kernel(const float* __restrict__ phases, float* __restrict__ out)
{
    __shared__ float sEz[2*6*NY];     // parity double-buffered Ez of own strip rows

    const int bk    = blockIdx.x;
    const int batch = bk / NSTRIP;
    const int s     = bk - batch * NSTRIP;
    const int r0    = (s * NX) / NSTRIP;
    const int r1    = ((s + 1) * NX) / NSTRIP;
    const int h     = r1 - r0;
    const bool hasA = (s > 0);
    const bool hasB = (s < NSTRIP - 1);
    const int tid   = threadIdx.x;
    const int bkA   = hasA ? bk - 1 : bk;
    const int bkB   = hasB ? bk + 1 : bk;

    const int  l    = tid / 100;
    const int  jq   = tid - l * 100;
    const bool act  = (tid < h * 100);
    const int  i    = r0 + l;
    const int  j0   = jq * 4;
    const int  o    = l * NY + j0;
    const bool topT = act && (l == 0);
    const bool botT = act && (l == h - 1);
    const bool spinA = topT && hasA;
    const bool spinB = botT && hasB;
    const bool upReg  = act && (l > 0);       // up Ez quad comes from smem
    const bool dnReg  = act && (l < h - 1);   // down Ez quad comes from smem

    for (int x = tid; x < 2*6*NY; x += TPB) sEz[x] = 0.f;

    // tag-fused slot pointers (parity offset added per step)
    const float4* plA = d_slB + bkA*NSLOT + 2*jq;   // above's bottom Ez slots
    const float4* plB = d_slT + bkB*NSLOT + 2*jq;   // below's top Ez slots
    float4*       psT = d_slT + bk*NSLOT + 2*jq;    // own top publish
    float4*       psB = d_slB + bk*NSLOT + 2*jq;    // own bottom publish

    // per-thread state
    float4 ez = {0,0,0,0}, hx = {0,0,0,0}, hy = {0,0,0,0}, hyU = {0,0,0,0};
    float4 dmp = {0,0,0,0}, iek = {0,0,0,0};
    float  hxW = 0.f, rU = 1.f, rL = 1.f;      // damp ratios for halo rows
    float4 Ssin = {0,0,0,0}, Scos = {0,0,0,0};
    bool hasSrc = false, hasDet = false;
    const bool edgeTop = topT && !hasA;        // global i==0
    const bool edgeL   = (jq == 0);

    if (act) {
        float di = d_damp1[i];
        dmp.x = di * d_damp1[j0];   dmp.y = di * d_damp1[j0+1];
        dmp.z = di * d_damp1[j0+2]; dmp.w = di * d_damp1[j0+3];
        iek = *(const float4*)&d_ie[i * NY + j0];
        if (i > 0)  rU = d_damp1[i - 1] / di;
        if (j0 > 0) rL = d_damp1[j0 - 1] / d_damp1[j0];
        if (i == SRC_I || i == DET_I) {
            float* ss = &Ssin.x; float* sc = &Scos.x;
            #pragma unroll
            for (int c = 0; c < 4; ++c) {
                int j = j0 + c;
                int p = (j + 10) / 80 - 1;
                int o2 = (j + 10) - 80 * (p + 1);
                bool inport = (p >= 0 && p < 4 && o2 < 20);
                if (inport && i == SRC_I) {
                    float ps = PI_F * phases[batch * 4 + p];
                    ss[c] = sinf(ps);     // angle at t=1 (tf=0)
                    sc[c] = cosf(ps);
                    hasSrc = true;
                }
                if (inport && i == DET_I) hasDet = true;
            }
        }
    }
    const float W  = (float)(2.0 * 3.14159265358979323846 * (12.5 / 1550.0));
    const float cW = cosf(W), sW = sinf(W);
    __syncthreads();

    for (unsigned t = 1; t <= STEPS; ++t) {
        const int qo = (int)((t - 1) & 1u) * (NBLK*NSLOT);
        const int po = (int)(t & 1u) * (NBLK*NSLOT);
        const float tf1  = (float)(t - 1);    // tag we need from neighbors
        const float tagf = (float)t;          // tag we publish
        const float* bufQ = sEz + (int)((t - 1) & 1u) * (6*NY);
        float*       bufP = sEz + (int)(t & 1u) * (6*NY);

        // ---- gather Ez(t-1) neighbors (smem first; overlap latency with polls) ----
        float  ezL = ez.x, ezE = ez.w;
        float4 ezU = ez,   ezD = ez;
        if (act) {
            if (!edgeL)   ezL = bufQ[o - 1];
            if (jq < 99)  ezE = bufQ[o + 4];
            if (upReg)    ezU = *(const float4*)&bufQ[o - NY];
            if (dnReg)    ezD = *(const float4*)&bufQ[o + NY];
        }
        if (spinA) {                 // poll tag-fused slots: data arrives with the tag
            float4 a0, a1;
            do { a0 = ld_vol_v4(plA + qo); a1 = ld_vol_v4(plA + qo + 1); }
            while (a0.x < tf1 || a0.w < tf1 || a1.x < tf1 || a1.w < tf1);
            ezU = make_float4(a0.y, a0.z, a1.y, a1.z);
        }
        if (spinB) {
            float4 b0, b1;
            do { b0 = ld_vol_v4(plB + qo); b1 = ld_vol_v4(plB + qo + 1); }
            while (b0.x < tf1 || b0.w < tf1 || b1.x < tf1 || b1.w < tf1);
            ezD = make_float4(b0.y, b0.z, b1.y, b1.z);
        }

        if (act) {
            // ---- halo H recurrences (use Ez(t-1)) ----
            hyU.x = rU * dmp.x * (hyU.x + 0.5f * (ez.x - ezU.x));
            hyU.y = rU * dmp.y * (hyU.y + 0.5f * (ez.y - ezU.y));
            hyU.z = rU * dmp.z * (hyU.z + 0.5f * (ez.z - ezU.z));
            hyU.w = rU * dmp.w * (hyU.w + 0.5f * (ez.w - ezU.w));
            hxW   = rL * dmp.x * (hxW   - 0.5f * (ez.x - ezL));

            // ---- own H ----
            hx.x = dmp.x * (hx.x - 0.5f * (ez.y - ez.x));
            hx.y = dmp.y * (hx.y - 0.5f * (ez.z - ez.y));
            hx.z = dmp.z * (hx.z - 0.5f * (ez.w - ez.z));
            hx.w = dmp.w * (hx.w - 0.5f * (ezE  - ez.w));
            hy.x = dmp.x * (hy.x + 0.5f * (ezD.x - ez.x));
            hy.y = dmp.y * (hy.y + 0.5f * (ezD.y - ez.y));
            hy.z = dmp.z * (hy.z + 0.5f * (ezD.z - ez.z));
            hy.w = dmp.w * (hy.w + 0.5f * (ezD.w - ez.w));

            // ---- E: all registers ----
            float4 hyUe = edgeTop ? hy : hyU;      // i==0: dHy_x = 0
            float  hxWe = edgeL   ? hx.x : hxW;    // j==0: dHx_y = 0
            ez.x = dmp.x * (ez.x + iek.x * ((hy.x - hyUe.x) - (hx.x - hxWe)));
            ez.y = dmp.y * (ez.y + iek.y * ((hy.y - hyUe.y) - (hx.y - hx.x)));
            ez.z = dmp.z * (ez.z + iek.z * ((hy.z - hyUe.z) - (hx.z - hx.y)));
            ez.w = dmp.w * (ez.w + iek.w * ((hy.w - hyUe.w) - (hx.w - hx.z)));

            if (hasSrc) {
                ez.x += Ssin.x;  ez.y += Ssin.y;  ez.z += Ssin.z;  ez.w += Ssin.w;
                float ns, nc;
                ns = Ssin.x * cW + Scos.x * sW; nc = Scos.x * cW - Ssin.x * sW; Ssin.x = ns; Scos.x = nc;
                ns = Ssin.y * cW + Scos.y * sW; nc = Scos.y * cW - Ssin.y * sW; Ssin.y = ns; Scos.y = nc;
                ns = Ssin.z * cW + Scos.z * sW; nc = Scos.z * cW - Ssin.z * sW; Ssin.z = ns; Scos.z = nc;
                ns = Ssin.w * cW + Scos.w * sW; nc = Scos.w * cW - Ssin.w * sW; Ssin.w = ns; Scos.w = nc;
            }

            // ---- publish boundary quads ASAP (membar orders our earlier halo reads: WAR-safe) ----
            if (topT | botT) asm volatile("membar.gl;" ::: "memory");
            if (topT) {
                st_vol_v4(psT + po,     make_float4(tagf, ez.x, ez.y, tagf));
                st_vol_v4(psT + po + 1, make_float4(tagf, ez.z, ez.w, tagf));
            }
            if (botT) {
                st_vol_v4(psB + po,     make_float4(tagf, ez.x, ez.y, tagf));
                st_vol_v4(psB + po + 1, make_float4(tagf, ez.z, ez.w, tagf));
            }
            *(float4*)&bufP[o] = ez;
        }
        __syncthreads();
    }

    // ---- detector: final Ez at row 370 lives in registers ----
    if (hasDet) {
        const float* ec = &ez.x;
        #pragma unroll
        for (int c = 0; c < 4; ++c) {
            int j = j0 + c;
            int p = (j + 10) / 80 - 1;
            int o2 = (j + 10) - 80 * (p + 1);
            if (p >= 0 && p < 4 && o2 < 20)
                out[batch * 80 + p * 20 + o2] = ec[c];
        }
    }
}

extern "C" void kernel_launch(void* const* d_in, const int* in_sizes, int n_in,
                              void* d_out, int out_size) {
    const float* phases = (const float*)d_in[0];   // (2,4)
    const float* radius = (const float*)d_in[1];   // (8,8)
    float* out = (float*)d_out;                    // (2,4,20)
    setup_kernel<<<(NC + 255) / 256, 256>>>(radius);
    fdtd_kernel<<<NBLK, TPB>>>(phases, out);
}